// round 8
// baseline (speedup 1.0000x reference)
#include <cuda_runtime.h>
#include <cuda_bf16.h>
#include <cstdint>

// InteractionBlock, persistent HMMA kernel, fully-overlapped pipeline.
//   d_chi = segment_sum(chi^2)                          [n,4]
//   h     = x @ W[0:128,:] + d_chi @ W[128:132,:] + b   [n,132]
//   a1      = h[:, :128]        -> out[0 : n*128]
//   chi_out = h[:,128+seg]*chi  -> out[n*128 : n*128+n*16]
//
// GEMM D[128,144] = A[128,128] @ B[144,128]^T, A/B split bf16 (hi,lo),
// acc = Ah*Bh + Ah*Bl + Al*Bh (fp32). d_chi K-tail exact in fp32 epilogue.
// Persistent CTAs; B in SMEM for whole kernel; next tile's x is LDG'd,
// converted and STS'd into the OTHER A buffer inside the MMA k-loop
// (software-pipelined one k-iter ahead). One __syncthreads per tile.
// Target plain sm_103 -> mma.sync only.

#define TM       128
#define NPAD     144
#define NCOLS    132
#define THREADS  256
#define B_BYTES  (NPAD * 256)

// ---- SMEM byte layout ----
// A buffer p at p*65536: hi at +0 (32768), lo at +32768
#define SM_B_HI   131072
#define SM_B_LO   (131072 + 36864)           // 167936
#define SM_DC     204800                     // 2 x 2048 (double)
#define SM_TH     208896                     // 2 x 2048 (double)
#define SM_WT2    212992                     // [NPAD][4] f32
#define SM_BIAS   215296                     // NPAD f32
#define SMEM_BYTES 215872

__device__ __align__(16) unsigned char g_Bimg[2 * B_BYTES];  // hi then lo
__device__ float g_Wt2[NPAD * 4];   // [c][s]
__device__ float g_bias[NPAD];

__device__ __forceinline__ uint32_t smem_u32(const void* p) {
    uint32_t a;
    asm("{ .reg .u64 t; cvta.to.shared.u64 t, %1; cvt.u32.u64 %0, t; }" : "=r"(a) : "l"(p));
    return a;
}
__device__ __forceinline__ uint32_t swoff(uint32_t r, uint32_t b) {
    return r * 256u + ((((b >> 4) ^ (r & 7u)) << 4) | (b & 15u));
}
__device__ __forceinline__ void ldm_x4(uint32_t* r, uint32_t addr) {
    asm volatile("ldmatrix.sync.aligned.m8n8.x4.shared.b16 {%0,%1,%2,%3}, [%4];"
                 : "=r"(r[0]), "=r"(r[1]), "=r"(r[2]), "=r"(r[3]) : "r"(addr));
}
__device__ __forceinline__ void ldm_x2(uint32_t* r, uint32_t addr) {
    asm volatile("ldmatrix.sync.aligned.m8n8.x2.shared.b16 {%0,%1}, [%2];"
                 : "=r"(r[0]), "=r"(r[1]) : "r"(addr));
}
__device__ __forceinline__ void mma16816(float* c, const uint32_t* a, const uint32_t* b) {
    asm volatile(
        "mma.sync.aligned.m16n8k16.row.col.f32.bf16.bf16.f32 "
        "{%0,%1,%2,%3}, {%4,%5,%6,%7}, {%8,%9}, {%0,%1,%2,%3};"
        : "+f"(c[0]), "+f"(c[1]), "+f"(c[2]), "+f"(c[3])
        : "r"(a[0]), "r"(a[1]), "r"(a[2]), "r"(a[3]), "r"(b[0]), "r"(b[1]));
}
// split 8 floats into bf16 hi/lo, store one uint4 each to A hi / A lo
__device__ __forceinline__ void cvt8_sts(float4 v0, float4 v1, uint32_t dsthi) {
    float f[8] = {v0.x, v0.y, v0.z, v0.w, v1.x, v1.y, v1.z, v1.w};
    uint32_t h[4], l[4];
    #pragma unroll
    for (int q = 0; q < 4; ++q) {
        __nv_bfloat16 h0 = __float2bfloat16(f[2*q]);
        __nv_bfloat16 h1 = __float2bfloat16(f[2*q+1]);
        __nv_bfloat16 l0 = __float2bfloat16(f[2*q]   - __bfloat162float(h0));
        __nv_bfloat16 l1 = __float2bfloat16(f[2*q+1] - __bfloat162float(h1));
        h[q] = (uint32_t)__bfloat16_as_ushort(h0) | ((uint32_t)__bfloat16_as_ushort(h1) << 16);
        l[q] = (uint32_t)__bfloat16_as_ushort(l0) | ((uint32_t)__bfloat16_as_ushort(l1) << 16);
    }
    asm volatile("st.shared.v4.b32 [%0], {%1,%2,%3,%4};"
                 :: "r"(dsthi), "r"(h[0]), "r"(h[1]), "r"(h[2]), "r"(h[3]));
    asm volatile("st.shared.v4.b32 [%0], {%1,%2,%3,%4};"
                 :: "r"(dsthi + 32768u), "r"(l[0]), "r"(l[1]), "r"(l[2]), "r"(l[3]));
}

// ============================================================================
// Prep kernel: swizzled B image (W^T hi/lo), transposed W tail, bias.
// ============================================================================
__global__ void prep_kernel(const float* __restrict__ W, const float* __restrict__ b) {
    int gid = blockIdx.x * blockDim.x + threadIdx.x;
    int nth = gridDim.x * blockDim.x;
    for (int idx = gid; idx < NPAD * 128; idx += nth) {
        int nrow = idx >> 7;
        int k    = idx & 127;
        float v = (nrow < NCOLS) ? W[k * NCOLS + nrow] : 0.f;
        __nv_bfloat16 hb = __float2bfloat16(v);
        __nv_bfloat16 lb = __float2bfloat16(v - __bfloat162float(hb));
        uint32_t off = swoff((uint32_t)nrow, (uint32_t)k * 2);
        *(__nv_bfloat16*)(g_Bimg + off) = hb;
        *(__nv_bfloat16*)(g_Bimg + B_BYTES + off) = lb;
    }
    for (int c = gid; c < NPAD; c += nth) {
        g_bias[c] = (c < NCOLS) ? b[c] : 0.f;
        #pragma unroll
        for (int s = 0; s < 4; ++s)
            g_Wt2[c * 4 + s] = (c < NCOLS) ? W[(128 + s) * NCOLS + c] : 0.f;
    }
}

__device__ __forceinline__ float4 dchi_of(float4 c0, float4 c1, float4 c2, float4 c3) {
    float d0 = c0.x*c0.x;
    float d1 = c0.y*c0.y + c0.z*c0.z + c0.w*c0.w;
    float d2 = c1.x*c1.x + c1.y*c1.y + c1.z*c1.z + c1.w*c1.w + c2.x*c2.x;
    float d3 = c2.y*c2.y + c2.z*c2.z + c2.w*c2.w
             + c3.x*c3.x + c3.y*c3.y + c3.z*c3.z + c3.w*c3.w;
    return make_float4(d0, d1, d2, d3);
}

// ============================================================================
// Main persistent kernel
// ============================================================================
__global__ __launch_bounds__(THREADS, 1)
void ib_pk(const float* __restrict__ x,
           const float* __restrict__ chi,
           float* __restrict__ out,
           int n, int ntiles)
{
    extern __shared__ __align__(16) unsigned char smem[];
    const uint32_t sb = smem_u32(smem);
    const int tid = threadIdx.x;
    const int wid = tid >> 5;
    const int lid = tid & 31;

    // ---- one-time B image + tail/bias (L2-hot) ----
    {
        const uint4* src = (const uint4*)g_Bimg;
        uint4* dst = (uint4*)(smem + SM_B_HI);
        for (int i = tid; i < (2 * B_BYTES) / 16; i += THREADS) dst[i] = src[i];
        float* wt = (float*)(smem + SM_WT2);
        for (int i = tid; i < 4 * NPAD; i += THREADS) wt[i] = g_Wt2[i];
        if (tid < NPAD) ((float*)(smem + SM_BIAS))[tid] = g_bias[tid];
    }

    // convert-lane coords: thread handles row cr, half ch8 (8 chunks of 8 floats)
    const int cr  = tid >> 1;
    const int ch8 = (tid & 1) * 8;
    const uint32_t crx = (uint32_t)(cr & 7);
    const uint32_t cvt_row_off = (uint32_t)cr * 256u;

    int t = blockIdx.x;
    int p = 0;

    // ---- prologue: convert tile t into buffer 0 ----
    {
        long long row = (long long)t * TM + cr;
        bool okx = row < n;
        const float* xp = x + row * 128 + (long long)ch8 * 8;
        #pragma unroll
        for (int c = 0; c < 8; ++c) {
            float4 v0 = make_float4(0,0,0,0), v1 = v0;
            if (okx) { v0 = *(const float4*)(xp + c*8); v1 = *(const float4*)(xp + c*8 + 4); }
            uint32_t off = cvt_row_off + ((((uint32_t)(ch8 + c)) ^ crx) << 4);
            cvt8_sts(v0, v1, sb + off);
        }
        if (tid < TM) {
            long long rowc = (long long)t * TM + tid;
            float4 c0 = make_float4(0,0,0,0), c1 = c0, c2 = c0, c3 = c0;
            if (rowc < n) {
                const float4* cp = (const float4*)(chi + rowc * 16);
                c0 = cp[0]; c1 = cp[1]; c2 = cp[2]; c3 = cp[3];
            }
            *(float4*)(smem + SM_DC + tid * 16) = dchi_of(c0, c1, c2, c3);
        }
    }
    __syncthreads();

    // warp-tile constants
    const int m0 = (wid & 3) * 32;
    const int n0 = (wid >> 2) * 72;
    const uint32_t rx = (uint32_t)(lid & 7);
    const uint32_t arow_off = (uint32_t)(m0 + (lid & 15)) * 256u;
    const uint32_t ahalf = (uint32_t)((lid >> 4) & 1);
    const uint32_t khalf = (uint32_t)((lid >> 3) & 1);
    const uint32_t b_base  = sb + SM_B_HI + (uint32_t)(n0 + (int)ahalf * 8 + (lid & 7)) * 256;
    const uint32_t b2_base = sb + SM_B_HI + (uint32_t)(n0 + 64 + (lid & 7)) * 256;
    const int tr = lid >> 2;
    const int tc = (lid & 3) * 2;

    const float* Bs  = (const float*)(smem + SM_BIAS);
    const float* Wt2 = (const float*)(smem + SM_WT2);
    float* out1 = out;
    float* out2 = out + (long long)n * 128;

    while (t < ntiles) {
        const long long row0 = (long long)t * TM;
        const int tn = t + gridDim.x;
        const bool hn = tn < ntiles;
        const uint32_t abase = sb + (uint32_t)(p << 16) + arow_off;
        const uint32_t wbase = sb + (uint32_t)((p ^ 1) << 16);

        // next-tile convert source
        long long nr = (long long)tn * TM + cr;
        bool okx = hn && (nr < n);
        const float* xp = x + nr * 128 + (long long)ch8 * 8;

        float acc[2][9][4];
        #pragma unroll
        for (int mt = 0; mt < 2; ++mt)
            #pragma unroll
            for (int nt = 0; nt < 9; ++nt)
                #pragma unroll
                for (int q = 0; q < 4; ++q) acc[mt][nt][q] = 0.f;

        float4 xc0a = make_float4(0,0,0,0), xc0b = xc0a;
        float4 xc1a = xc0a, xc1b = xc0a;
        if (okx) { xc0a = *(const float4*)xp; xc0b = *(const float4*)(xp + 4); }

        #pragma unroll
        for (int k = 0; k < 8; ++k) {
            uint32_t ah[2][4], al[2][4], bh[9][2], bl[9][2];
            const uint32_t ac = (((uint32_t)(2 * k) + ahalf) ^ rx) << 4;
            #pragma unroll
            for (int mt = 0; mt < 2; ++mt) {
                uint32_t a = abase + (uint32_t)mt * 4096 + ac;
                ldm_x4(ah[mt], a);
                ldm_x4(al[mt], a + 32768u);
            }
            const uint32_t bc = (((uint32_t)(2 * k) + khalf) ^ rx) << 4;
            #pragma unroll
            for (int p4 = 0; p4 < 4; ++p4) {
                uint32_t a = b_base + (uint32_t)p4 * 4096 + bc;
                uint32_t r4[4];
                ldm_x4(r4, a);
                bh[2*p4][0] = r4[0]; bh[2*p4][1] = r4[1];
                bh[2*p4+1][0] = r4[2]; bh[2*p4+1][1] = r4[3];
                ldm_x4(r4, a + (SM_B_LO - SM_B_HI));
                bl[2*p4][0] = r4[0]; bl[2*p4][1] = r4[1];
                bl[2*p4+1][0] = r4[2]; bl[2*p4+1][1] = r4[3];
            }
            if (n0 == 0) {
                uint32_t a2 = b2_base + bc;
                ldm_x2(bh[8], a2);
                ldm_x2(bl[8], a2 + (SM_B_LO - SM_B_HI));
            }
            // issue next x chunk LDG (one k-iter ahead)
            if (k < 7) {
                xc1a = make_float4(0,0,0,0); xc1b = xc1a;
                if (okx) {
                    xc1a = *(const float4*)(xp + (k+1)*8);
                    xc1b = *(const float4*)(xp + (k+1)*8 + 4);
                }
            }
            // pass1: Ah*Bh
            #pragma unroll
            for (int nt = 0; nt < 9; ++nt)
                if (nt < 8 || n0 == 0) {
                    mma16816(acc[0][nt], ah[0], bh[nt]);
                    mma16816(acc[1][nt], ah[1], bh[nt]);
                }
            // convert current x chunk into A[next] (overlaps tensor pipe)
            if (hn) {
                uint32_t off = cvt_row_off + ((((uint32_t)(ch8 + k)) ^ crx) << 4);
                cvt8_sts(xc0a, xc0b, wbase + off);
            }
            // pass2: Ah*Bl
            #pragma unroll
            for (int nt = 0; nt < 9; ++nt)
                if (nt < 8 || n0 == 0) {
                    mma16816(acc[0][nt], ah[0], bl[nt]);
                    mma16816(acc[1][nt], ah[1], bl[nt]);
                }
            // pass3: Al*Bh
            #pragma unroll
            for (int nt = 0; nt < 9; ++nt)
                if (nt < 8 || n0 == 0) {
                    mma16816(acc[0][nt], al[0], bh[nt]);
                    mma16816(acc[1][nt], al[1], bh[nt]);
                }
            xc0a = xc1a; xc0b = xc1b;
        }

        // ---- chi LDG for next tile (latency hidden under epilogue) ----
        float4 nc0 = make_float4(0,0,0,0), nc1 = nc0, nc2 = nc0, nc3 = nc0;
        if (tid < TM && hn) {
            long long rowc = (long long)tn * TM + tid;
            if (rowc < n) {
                const float4* cp = (const float4*)(chi + rowc * 16);
                nc0 = cp[0]; nc1 = cp[1]; nc2 = cp[2]; nc3 = cp[3];
            }
        }

        // ---- epilogue: bias + exact d_chi tail; a1 -> gmem, tail -> Th ----
        const float* Dc = (const float*)(smem + SM_DC + p * 2048);
        float* Th = (float*)(smem + SM_TH + p * 2048);
        #pragma unroll
        for (int mt = 0; mt < 2; ++mt) {
            const int r = m0 + mt * 16 + tr;
            const long long rowA = row0 + r;
            const long long rowB = rowA + 8;
            const float4 dca = *(const float4*)&Dc[r * 4];
            const float4 dcb = *(const float4*)&Dc[(r + 8) * 4];
            #pragma unroll
            for (int nt = 0; nt < 9; ++nt) {
                const int c = n0 + nt * 8 + tc;
                if (c < NCOLS) {
                    float2 bi = *(const float2*)&Bs[c];
                    float4 w0 = *(const float4*)&Wt2[c * 4];
                    float4 w1 = *(const float4*)&Wt2[(c + 1) * 4];
                    float h0 = acc[mt][nt][0] + bi.x;
                    float h1 = acc[mt][nt][1] + bi.y;
                    float h2 = acc[mt][nt][2] + bi.x;
                    float h3 = acc[mt][nt][3] + bi.y;
                    h0 = fmaf(dca.x, w0.x, h0); h0 = fmaf(dca.y, w0.y, h0);
                    h0 = fmaf(dca.z, w0.z, h0); h0 = fmaf(dca.w, w0.w, h0);
                    h1 = fmaf(dca.x, w1.x, h1); h1 = fmaf(dca.y, w1.y, h1);
                    h1 = fmaf(dca.z, w1.z, h1); h1 = fmaf(dca.w, w1.w, h1);
                    h2 = fmaf(dcb.x, w0.x, h2); h2 = fmaf(dcb.y, w0.y, h2);
                    h2 = fmaf(dcb.z, w0.z, h2); h2 = fmaf(dcb.w, w0.w, h2);
                    h3 = fmaf(dcb.x, w1.x, h3); h3 = fmaf(dcb.y, w1.y, h3);
                    h3 = fmaf(dcb.z, w1.z, h3); h3 = fmaf(dcb.w, w1.w, h3);
                    if (c < 128) {
                        if (rowA < n) *(float2*)(out1 + rowA * 128 + c) = make_float2(h0, h1);
                        if (rowB < n) *(float2*)(out1 + rowB * 128 + c) = make_float2(h2, h3);
                    } else {
                        *(float2*)&Th[r * 4 + (c - 128)]       = make_float2(h0, h1);
                        *(float2*)&Th[(r + 8) * 4 + (c - 128)] = make_float2(h2, h3);
                    }
                }
            }
        }

        // ---- d_chi for next tile into Dc[next] ----
        if (tid < TM && hn)
            *(float4*)(smem + SM_DC + (p ^ 1) * 2048 + tid * 16) = dchi_of(nc0, nc1, nc2, nc3);

        __syncthreads();

        // ---- chi_out for tile t (Th has full h for cols 128..131) ----
        {
            long long row = row0 + cr;
            if (row < n) {
                const float4 th = *(const float4*)((const float*)(smem + SM_TH + p * 2048) + cr * 4);
                const float4 ca = *(const float4*)(chi + row * 16 + ch8);
                const float4 cb = *(const float4*)(chi + row * 16 + ch8 + 4);
                float s0, s1, s4;
                if (ch8 == 0) { s0 = th.x; s1 = th.y; s4 = th.z; }
                else          { s0 = th.z; s1 = th.w; s4 = th.w; }
                float4 o0 = make_float4(s0 * ca.x, s1 * ca.y, s1 * ca.z, s1 * ca.w);
                float4 o1 = make_float4(s4 * cb.x, s4 * cb.y, s4 * cb.z, s4 * cb.w);
                float* dst = out2 + row * 16 + ch8;
                *(float4*)dst = o0;
                *(float4*)(dst + 4) = o1;
            }
        }

        t = tn;
        p ^= 1;
    }
}

extern "C" void kernel_launch(void* const* d_in, const int* in_sizes, int n_in,
                              void* d_out, int out_size)
{
    const float* x   = (const float*)d_in[0];
    const float* chi = (const float*)d_in[1];
    // d_in[2] = point_mask (unused by reference computation)
    const float* W   = (const float*)d_in[3];
    const float* b   = (const float*)d_in[4];
    float* out = (float*)d_out;

    const int n = in_sizes[2];
    const int ntiles = (n + TM - 1) / TM;

    int dev = 0, nsm = 148;
    cudaGetDevice(&dev);
    cudaDeviceGetAttribute(&nsm, cudaDevAttrMultiProcessorCount, dev);

    cudaFuncSetAttribute(ib_pk,
                         cudaFuncAttributeMaxDynamicSharedMemorySize, SMEM_BYTES);

    prep_kernel<<<64, THREADS>>>(W, b);
    int grid = ntiles < nsm ? ntiles : nsm;
    ib_pk<<<grid, THREADS, SMEM_BYTES>>>(x, chi, out, n, ntiles);
}

// round 11
// speedup vs baseline: 1.0131x; 1.0131x over previous
#include <cuda_runtime.h>
#include <cuda_bf16.h>
#include <cstdint>

// InteractionBlock, persistent HMMA kernel (R7 pipeline, 512 threads).
//   d_chi = segment_sum(chi^2)                          [n,4]
//   h     = x @ W[0:128,:] + d_chi @ W[128:132,:] + b   [n,132]
//   a1      = h[:, :128]        -> out[0 : n*128]
//   chi_out = h[:,128+seg]*chi  -> out[n*128 : n*128+n*16]
//
// GEMM D[128,144] = A[128,128] @ B[144,128]^T, A/B split bf16 (hi,lo),
// acc = Ah*Bh + Ah*Bl + Al*Bh (fp32). d_chi K-tail exact fp32 in epilogue.
// Persistent CTAs; B in SMEM whole kernel; x/chi staged via cp.async,
// prefetched one tile ahead. 16 warps: 8 row-groups x 2 col-groups.
// Target plain sm_103 -> mma.sync only.

#define TM       128
#define NPAD     144
#define NCOLS    132
#define THREADS  512
#define B_BYTES  (NPAD * 256)

// ---- SMEM byte layout ----
#define SM_A_HI   0
#define SM_A_LO   32768
#define SM_B_HI   65536
#define SM_B_LO   (65536 + 36864)            // 102400
#define SM_XSTG   139264                     // 128 x 512B
#define SM_CSTG   204800                     // 128 x 80B
#define SM_DCHI   215040                     // 128 x 4 f32
#define SM_TH     217088                     // 128 x 4 f32 (full h, cols 128..131)
#define SM_WT2    219136                     // [NPAD][4] f32
#define SM_BIAS   221440                     // NPAD f32
#define SMEM_BYTES 222016

__device__ __align__(16) unsigned char g_Bimg[2 * B_BYTES];  // hi then lo
__device__ float g_Wt2[NPAD * 4];
__device__ float g_bias[NPAD];

__device__ __forceinline__ uint32_t smem_u32(const void* p) {
    uint32_t a;
    asm("{ .reg .u64 t; cvta.to.shared.u64 t, %1; cvt.u32.u64 %0, t; }" : "=r"(a) : "l"(p));
    return a;
}
__device__ __forceinline__ uint32_t swoff(uint32_t r, uint32_t b) {
    return r * 256u + ((((b >> 4) ^ (r & 7u)) << 4) | (b & 15u));
}
__device__ __forceinline__ void ldm_x4(uint32_t* r, uint32_t addr) {
    asm volatile("ldmatrix.sync.aligned.m8n8.x4.shared.b16 {%0,%1,%2,%3}, [%4];"
                 : "=r"(r[0]), "=r"(r[1]), "=r"(r[2]), "=r"(r[3]) : "r"(addr));
}
__device__ __forceinline__ void ldm_x2(uint32_t* r, uint32_t addr) {
    asm volatile("ldmatrix.sync.aligned.m8n8.x2.shared.b16 {%0,%1}, [%2];"
                 : "=r"(r[0]), "=r"(r[1]) : "r"(addr));
}
__device__ __forceinline__ void mma16816(float* c, const uint32_t* a, const uint32_t* b) {
    asm volatile(
        "mma.sync.aligned.m16n8k16.row.col.f32.bf16.bf16.f32 "
        "{%0,%1,%2,%3}, {%4,%5,%6,%7}, {%8,%9}, {%0,%1,%2,%3};"
        : "+f"(c[0]), "+f"(c[1]), "+f"(c[2]), "+f"(c[3])
        : "r"(a[0]), "r"(a[1]), "r"(a[2]), "r"(a[3]), "r"(b[0]), "r"(b[1]));
}
__device__ __forceinline__ void cp16(uint32_t dst, const void* src, uint32_t bytes) {
    asm volatile("cp.async.cg.shared.global [%0], [%1], 16, %2;"
                 :: "r"(dst), "l"(src), "r"(bytes) : "memory");
}

// ============================================================================
// Prep kernel: swizzled B image (W^T hi/lo), transposed W tail, bias.
// ============================================================================
__global__ void prep_kernel(const float* __restrict__ W, const float* __restrict__ b) {
    int gid = blockIdx.x * blockDim.x + threadIdx.x;
    int nth = gridDim.x * blockDim.x;
    for (int idx = gid; idx < NPAD * 128; idx += nth) {
        int nrow = idx >> 7;
        int k    = idx & 127;
        float v = (nrow < NCOLS) ? W[k * NCOLS + nrow] : 0.f;
        __nv_bfloat16 hb = __float2bfloat16(v);
        __nv_bfloat16 lb = __float2bfloat16(v - __bfloat162float(hb));
        uint32_t off = swoff((uint32_t)nrow, (uint32_t)k * 2);
        *(__nv_bfloat16*)(g_Bimg + off) = hb;
        *(__nv_bfloat16*)(g_Bimg + B_BYTES + off) = lb;
    }
    for (int c = gid; c < NPAD; c += nth) {
        g_bias[c] = (c < NCOLS) ? b[c] : 0.f;
        #pragma unroll
        for (int s = 0; s < 4; ++s)
            g_Wt2[c * 4 + s] = (c < NCOLS) ? W[(128 + s) * NCOLS + c] : 0.f;
    }
}

__device__ __forceinline__ void prefetch_tile(const float* x, const float* chi,
                                              int n, long long row0,
                                              uint32_t sb, int tid) {
    #pragma unroll
    for (int it = 0; it < 8; ++it) {
        int i   = tid + THREADS * it;
        int r   = i >> 5;
        int c16 = i & 31;
        long long row = row0 + r;
        bool ok = row < n;
        const float* src = x + (ok ? row * 128 : 0) + c16 * 4;
        cp16(sb + SM_XSTG + r * 512 + c16 * 16, src, ok ? 16u : 0u);
    }
    {
        int r = tid >> 2;
        int q = tid & 3;
        long long row = row0 + r;
        bool ok = row < n;
        const float* src = chi + (ok ? row * 16 : 0) + q * 4;
        cp16(sb + SM_CSTG + r * 80 + q * 16, src, ok ? 16u : 0u);
    }
    asm volatile("cp.async.commit_group;" ::: "memory");
}

// ============================================================================
// Main persistent kernel
// ============================================================================
__global__ __launch_bounds__(THREADS, 1)
void ib_pk(const float* __restrict__ x,
           const float* __restrict__ chi,
           float* __restrict__ out,
           int n, int ntiles)
{
    extern __shared__ __align__(16) unsigned char smem[];
    const uint32_t sb = smem_u32(smem);
    const int tid = threadIdx.x;
    const int wid = tid >> 5;
    const int lid = tid & 31;

    int t = blockIdx.x;
    if (t < ntiles)
        prefetch_tile(x, chi, n, (long long)t * TM, sb, tid);
    else
        asm volatile("cp.async.commit_group;" ::: "memory");

    // ---- one-time B image + tail/bias (L2-hot) ----
    {
        const uint4* src = (const uint4*)g_Bimg;
        uint4* dst = (uint4*)(smem + SM_B_HI);
        for (int i = tid; i < (2 * B_BYTES) / 16; i += THREADS) dst[i] = src[i];
        float* wt = (float*)(smem + SM_WT2);
        for (int i = tid; i < 4 * NPAD; i += THREADS) wt[i] = g_Wt2[i];
        if (tid < NPAD) ((float*)(smem + SM_BIAS))[tid] = g_bias[tid];
    }

    // ---- warp tiling: 8 row-groups x 2 col-groups ----
    const int m0 = (wid & 7) * 16;
    const int n0 = (wid >> 3) * 72;
    const uint32_t rx = (uint32_t)(lid & 7);
    const uint32_t a_base = sb + SM_A_HI + (uint32_t)(m0 + (lid & 15)) * 256;
    const uint32_t ahalf = (uint32_t)((lid >> 4) & 1);
    const uint32_t khalf = (uint32_t)((lid >> 3) & 1);
    const uint32_t b_base  = sb + SM_B_HI + (uint32_t)(n0 + (int)ahalf * 8 + (lid & 7)) * 256;
    const uint32_t b2_base = sb + SM_B_HI + (uint32_t)(n0 + 64 + (lid & 7)) * 256;
    const int tr = lid >> 2;
    const int tc = (lid & 3) * 2;

    const float* Bs  = (const float*)(smem + SM_BIAS);
    const float* Wt2 = (const float*)(smem + SM_WT2);
    float* out1 = out;
    float* out2 = out + (long long)n * 128;

    while (t < ntiles) {
        const long long row0 = (long long)t * TM;
        asm volatile("cp.async.wait_group 0;" ::: "memory");
        __syncthreads();

        // ---- convert stage -> A hi/lo (swizzled bf16) ----
        #pragma unroll
        for (int it = 0; it < 8; ++it) {
            int i  = tid + THREADS * it;
            int r  = i >> 5;
            int c4 = (i & 31) << 2;
            float4 v = *(const float4*)(smem + SM_XSTG + r * 512 + c4 * 4);
            float f[4] = {v.x, v.y, v.z, v.w};
            uint32_t hp[2], lp[2];
            #pragma unroll
            for (int q = 0; q < 2; ++q) {
                __nv_bfloat16 h0 = __float2bfloat16(f[2*q]);
                __nv_bfloat16 h1 = __float2bfloat16(f[2*q+1]);
                __nv_bfloat16 l0 = __float2bfloat16(f[2*q]   - __bfloat162float(h0));
                __nv_bfloat16 l1 = __float2bfloat16(f[2*q+1] - __bfloat162float(h1));
                hp[q] = (uint32_t)__bfloat16_as_ushort(h0) | ((uint32_t)__bfloat16_as_ushort(h1) << 16);
                lp[q] = (uint32_t)__bfloat16_as_ushort(l0) | ((uint32_t)__bfloat16_as_ushort(l1) << 16);
            }
            uint32_t off = swoff((uint32_t)r, (uint32_t)c4 * 2);
            *(uint2*)(smem + SM_A_HI + off) = make_uint2(hp[0], hp[1]);
            *(uint2*)(smem + SM_A_LO + off) = make_uint2(lp[0], lp[1]);
        }
        // ---- d_chi from chi stage ----
        if (tid < TM) {
            const int r = tid;
            const float4* cs = (const float4*)(smem + SM_CSTG + r * 80);
            float4 c0 = cs[0], c1 = cs[1], c2 = cs[2], c3 = cs[3];
            float d0 = c0.x*c0.x;
            float d1 = c0.y*c0.y + c0.z*c0.z + c0.w*c0.w;
            float d2 = c1.x*c1.x + c1.y*c1.y + c1.z*c1.z + c1.w*c1.w + c2.x*c2.x;
            float d3 = c2.y*c2.y + c2.z*c2.z + c2.w*c2.w
                     + c3.x*c3.x + c3.y*c3.y + c3.z*c3.z + c3.w*c3.w;
            *(float4*)(smem + SM_DCHI + r * 16) = make_float4(d0, d1, d2, d3);
        }
        __syncthreads();

        // ---- prefetch next tile while MMA/epilogue run ----
        const int tn = t + gridDim.x;
        if (tn < ntiles)
            prefetch_tile(x, chi, n, (long long)tn * TM, sb, tid);
        else
            asm volatile("cp.async.commit_group;" ::: "memory");

        // ---- MMA: 3-term bf16 split (9 nt for col-group 0, 8 for group 1) ----
        float acc[9][4];
        #pragma unroll
        for (int nt = 0; nt < 9; ++nt)
            #pragma unroll
            for (int q = 0; q < 4; ++q) acc[nt][q] = 0.f;

        #pragma unroll
        for (int k = 0; k < 8; ++k) {
            uint32_t ah[4], al[4], bh[9][2], bl[9][2];
            const uint32_t ac = (((uint32_t)(2 * k) + ahalf) ^ rx) << 4;
            {
                uint32_t a = a_base + ac;
                ldm_x4(ah, a);
                ldm_x4(al, a + 32768u);
            }
            const uint32_t bc = (((uint32_t)(2 * k) + khalf) ^ rx) << 4;
            #pragma unroll
            for (int p4 = 0; p4 < 4; ++p4) {
                uint32_t a = b_base + (uint32_t)p4 * 4096 + bc;
                uint32_t r4[4];
                ldm_x4(r4, a);
                bh[2*p4][0] = r4[0]; bh[2*p4][1] = r4[1];
                bh[2*p4+1][0] = r4[2]; bh[2*p4+1][1] = r4[3];
                ldm_x4(r4, a + (SM_B_LO - SM_B_HI));
                bl[2*p4][0] = r4[0]; bl[2*p4][1] = r4[1];
                bl[2*p4+1][0] = r4[2]; bl[2*p4+1][1] = r4[3];
            }
            if (n0 == 0) {
                uint32_t a2 = b2_base + bc;
                ldm_x2(bh[8], a2);
                ldm_x2(bl[8], a2 + (SM_B_LO - SM_B_HI));
            }
            #pragma unroll
            for (int nt = 0; nt < 9; ++nt)
                if (nt < 8 || n0 == 0) mma16816(acc[nt], ah, bh[nt]);
            #pragma unroll
            for (int nt = 0; nt < 9; ++nt)
                if (nt < 8 || n0 == 0) mma16816(acc[nt], ah, bl[nt]);
            #pragma unroll
            for (int nt = 0; nt < 9; ++nt)
                if (nt < 8 || n0 == 0) mma16816(acc[nt], al, bh[nt]);
        }

        // ---- epilogue: bias + exact d_chi tail; a1 -> gmem, cols 128..131 -> Th ----
        {
            const float* Dc = (const float*)(smem + SM_DCHI);
            float* Th = (float*)(smem + SM_TH);
            const int r = m0 + tr;
            const long long rowA = row0 + r;
            const long long rowB = rowA + 8;
            const float4 dca = *(const float4*)&Dc[r * 4];
            const float4 dcb = *(const float4*)&Dc[(r + 8) * 4];
            #pragma unroll
            for (int nt = 0; nt < 9; ++nt) {
                const int c = n0 + nt * 8 + tc;
                if (c < NCOLS) {
                    float2 bi = *(const float2*)&Bs[c];
                    float4 w0 = *(const float4*)&Wt2[c * 4];
                    float4 w1 = *(const float4*)&Wt2[(c + 1) * 4];
                    float h0 = acc[nt][0] + bi.x;
                    float h1 = acc[nt][1] + bi.y;
                    float h2 = acc[nt][2] + bi.x;
                    float h3 = acc[nt][3] + bi.y;
                    h0 = fmaf(dca.x, w0.x, h0); h0 = fmaf(dca.y, w0.y, h0);
                    h0 = fmaf(dca.z, w0.z, h0); h0 = fmaf(dca.w, w0.w, h0);
                    h1 = fmaf(dca.x, w1.x, h1); h1 = fmaf(dca.y, w1.y, h1);
                    h1 = fmaf(dca.z, w1.z, h1); h1 = fmaf(dca.w, w1.w, h1);
                    h2 = fmaf(dcb.x, w0.x, h2); h2 = fmaf(dcb.y, w0.y, h2);
                    h2 = fmaf(dcb.z, w0.z, h2); h2 = fmaf(dcb.w, w0.w, h2);
                    h3 = fmaf(dcb.x, w1.x, h3); h3 = fmaf(dcb.y, w1.y, h3);
                    h3 = fmaf(dcb.z, w1.z, h3); h3 = fmaf(dcb.w, w1.w, h3);
                    if (c < 128) {
                        if (rowA < n) *(float2*)(out1 + rowA * 128 + c) = make_float2(h0, h1);
                        if (rowB < n) *(float2*)(out1 + rowB * 128 + c) = make_float2(h2, h3);
                    } else {
                        *(float2*)&Th[r * 4 + (c - 128)]       = make_float2(h0, h1);
                        *(float2*)&Th[(r + 8) * 4 + (c - 128)] = make_float2(h2, h3);
                    }
                }
            }
        }
        __syncthreads();

        // ---- chi_out (chi re-read from gmem, L2-hot) ----
        {
            const float* Th = (const float*)(smem + SM_TH);
            #pragma unroll
            for (int it = 0; it < 4; ++it) {
                int i = tid + THREADS * it;     // 0..2047
                int r = i >> 4;
                int m = i & 15;
                long long row = row0 + r;
                if (row < n) {
                    int s = (m == 0) ? 0 : (m < 4) ? 1 : (m < 9) ? 2 : 3;
                    out2[row * 16 + m] = Th[r * 4 + s] * chi[row * 16 + m];
                }
            }
        }
        t = tn;
    }
}

extern "C" void kernel_launch(void* const* d_in, const int* in_sizes, int n_in,
                              void* d_out, int out_size)
{
    const float* x   = (const float*)d_in[0];
    const float* chi = (const float*)d_in[1];
    // d_in[2] = point_mask (unused by reference computation)
    const float* W   = (const float*)d_in[3];
    const float* b   = (const float*)d_in[4];
    float* out = (float*)d_out;

    const int n = in_sizes[2];
    const int ntiles = (n + TM - 1) / TM;

    int dev = 0, nsm = 148;
    cudaGetDevice(&dev);
    cudaDeviceGetAttribute(&nsm, cudaDevAttrMultiProcessorCount, dev);

    cudaFuncSetAttribute(ib_pk,
                         cudaFuncAttributeMaxDynamicSharedMemorySize, SMEM_BYTES);

    prep_kernel<<<64, 256>>>(W, b);
    int grid = ntiles < nsm ? ntiles : nsm;
    ib_pk<<<grid, THREADS, SMEM_BYTES>>>(x, chi, out, n, ntiles);
}